// round 13
// baseline (speedup 1.0000x reference)
#include <cuda_runtime.h>
#include <cuda_fp16.h>
#include <cstdint>

// ResidualKANBlock via mma.sync m16n8k16 f16 with F16 ACCUMULATORS (R11),
// promoted to f32 once per chunk. Dense K=1792 (14 slots/dim, 8-dim chunks),
// warp n-split (TM=64), 16 chunks, W double-buffer cp.async, PITCH=240.

#define NTOK   65536
#define TM     64
#define NCTA   (NTOK / TM)            // 1024
#define NCHUNK 16                     // 8 input dims per chunk (K=112 slots)
#define LN_EPS 1e-5f

#define PITCH  240                    // bytes/row; 16B-aligned, bank-safe
#define ABUF   (64 * PITCH)
#define WBUF   (128 * PITCH)
#define SM_A0  0
#define SM_A1  ABUF
#define SM_W   (2 * ABUF)
#define SM_GB  (SM_W + 2 * WBUF)
#define SM_EPI (SM_GB + 1024)
#define SM_TOT (SM_EPI + 1024)        // ~94.2 KB -> occupancy 2

__device__ float          g_xT[128u * 65536u];
__device__ unsigned short g_W[NCHUNK * 128 * (PITCH/2)];

__device__ __forceinline__ unsigned s2u(const void* p) {
    unsigned r;
    asm("{ .reg .u64 t; cvta.to.shared.u64 t, %1; cvt.u32.u64 %0, t; }" : "=r"(r) : "l"(p));
    return r;
}

#define LDSM_X4(r, a) \
    asm volatile("ldmatrix.sync.aligned.m8n8.x4.shared.b16 {%0,%1,%2,%3}, [%4];" \
                 : "=r"((r)[0]), "=r"((r)[1]), "=r"((r)[2]), "=r"((r)[3]) : "r"(a))
// f16-accumulator MMA: D/C are 2 packed-half2 regs
#define MMA16816H(d, a, b0, b1) \
    asm volatile("mma.sync.aligned.m16n8k16.row.col.f16.f16.f16.f16 " \
                 "{%0,%1}, {%2,%3,%4,%5}, {%6,%7}, {%0,%1};" \
                 : "+r"((d)[0]), "+r"((d)[1]) \
                 : "r"((a)[0]), "r"((a)[1]), "r"((a)[2]), "r"((a)[3]), "r"(b0), "r"(b1))
#define CPASYNC16(dst, src) \
    asm volatile("cp.async.cg.shared.global [%0], [%1], 16;" :: "r"(dst), "l"(src) : "memory")

// ------------------------------------------------------------- prep kernels
__global__ void transpose_x(const float* __restrict__ x) {
    // 32 tokens x 128 dims per block; float4 both phases
    __shared__ float t[32][129];
    const int tid = threadIdx.x;
    const int tok0 = blockIdx.x * 32;
    const float4* x4 = (const float4*)x;
    #pragma unroll
    for (int i = 0; i < 4; ++i) {
        int idx = tid + 256 * i;                  // 0..1023
        int row = idx >> 5, c4 = idx & 31;
        float4 v = x4[(size_t)(tok0 + row) * 32 + c4];
        t[row][c4 * 4 + 0] = v.x; t[row][c4 * 4 + 1] = v.y;
        t[row][c4 * 4 + 2] = v.z; t[row][c4 * 4 + 3] = v.w;
    }
    __syncthreads();
    const int d = tid >> 1, h = tid & 1;          // dim, token-half
    #pragma unroll
    for (int q = 0; q < 4; ++q) {
        int r = h * 16 + q * 4;
        float4 v = make_float4(t[r][d], t[r + 1][d], t[r + 2][d], t[r + 3][d]);
        *(float4*)(g_xT + (size_t)d * 65536 + tok0 + r) = v;
    }
}

__global__ void prep_w(const float* __restrict__ base_w,
                       const float* __restrict__ spline_w) {
    int idx = blockIdx.x * blockDim.x + threadIdx.x;
    if (idx >= NCHUNK * 128 * (PITCH / 2)) return;
    int c = idx / (128 * (PITCH / 2));
    int r = idx % (128 * (PITCH / 2));
    int n = r / (PITCH / 2);
    int s = r % (PITCH / 2);
    float v = 0.f;
    if (s < 112) {
        int d = s / 14, jj = s - d * 14, i = 8 * c + d;
        if (jj < 13) v = spline_w[(size_t)n * 1664 + i * 13 + jj];
        else         v = base_w[n * 128 + i];
    }
    g_W[(size_t)c * (128 * (PITCH/2)) + n * (PITCH/2) + s] =
        __half_as_ushort(__float2half_rn(v));
}

// --------------------------------------------------------------- main kernel
__global__ void __launch_bounds__(256, 2)
kan_mma(const float* __restrict__ x, const float* __restrict__ gamma,
        const float* __restrict__ beta, float* __restrict__ out)
{
    extern __shared__ unsigned char smem[];
    const unsigned sb = s2u(smem);
    const int tid = threadIdx.x;
    const int w = tid >> 5, l = tid & 31;
    const int g = w >> 1, h = w & 1;
    const int tok = tid & 63, p = tid >> 6;
    const int tokbase = blockIdx.x * TM;

    if (tid < 128) {
        float2 gb = make_float2(gamma[tid], beta[tid]);
        *(float2*)(smem + SM_GB + tid * 8) = gb;
    }

    const unsigned paBase = (unsigned)(g * 16 + (l & 15)) * PITCH + ((l >> 4) & 1) * 16;
    const unsigned pbBase = (unsigned)(((l >> 4) & 1) * 8 + (l & 7)) * PITCH + ((l >> 3) & 1) * 16;
    const unsigned hOff = (unsigned)h * 64 * PITCH;

    float acc[8][4];
    #pragma unroll
    for (int t = 0; t < 8; ++t)
        acc[t][0] = acc[t][1] = acc[t][2] = acc[t][3] = 0.f;

    auto cpW = [&](int c, int buf) {
        const char* src = (const char*)(g_W + (size_t)c * (128 * (PITCH/2)));
        unsigned dst = sb + SM_W + buf * WBUF;
        #pragma unroll
        for (int k = 0; k < 8; ++k) {
            int i16 = tid + 256 * k;
            if (i16 < WBUF / 16) CPASYNC16(dst + 16 * i16, src + 16 * i16);
        }
        asm volatile("cp.async.commit_group;" ::: "memory");
    };
    cpW(0, 0);

    const float* xpa = g_xT + (size_t)p * 65536 + tokbase + tok;
    const float* xpb = g_xT + (size_t)(p + 4) * 65536 + tokbase + tok;

    auto buildA = [&](unsigned aoff, float xa, float xb) {
        #pragma unroll
        for (int d2 = 0; d2 < 2; ++d2) {
            float xv = d2 ? xb : xa;
            int dim = p + d2 * 4;
            float ex = __expf(-xv);
            float s  = __fdividef(xv, 1.f + ex);
            float t5 = fmaf(xv, 5.f, 8.f);
            float cf = floorf(t5);
            int   ci = (int)cf;
            float u  = t5 - cf;
            float um = 1.f - u;
            float u2 = u * u, um2 = um * um;
            float b0 = um2 * um * (1.f / 6.f);
            float b3 = u2 * u * (1.f / 6.f);
            float b1 = fmaf(u2, fmaf(u, 0.5f, -1.f), 2.f / 3.f);
            float b2 = fmaf(um2, fmaf(um, 0.5f, -1.f), 2.f / 3.f);
            unsigned char* rowb = smem + aoff + (unsigned)tok * PITCH + dim * 28;
            #pragma unroll
            for (int z = 0; z < 7; ++z) ((unsigned*)rowb)[z] = 0u;
            unsigned short* r16 = (unsigned short*)rowb;
            r16[13] = __half_as_ushort(__float2half_rn(s));
            int j0 = ci - 3;
            unsigned short h0 = __half_as_ushort(__float2half_rn(b0));
            unsigned short h1 = __half_as_ushort(__float2half_rn(b1));
            unsigned short h2 = __half_as_ushort(__float2half_rn(b2));
            unsigned short h3 = __half_as_ushort(__float2half_rn(b3));
            if ((unsigned)(j0 + 0) <= 12u) r16[j0 + 0] = h0;
            if ((unsigned)(j0 + 1) <= 12u) r16[j0 + 1] = h1;
            if ((unsigned)(j0 + 2) <= 12u) r16[j0 + 2] = h2;
            if ((unsigned)(j0 + 3) <= 12u) r16[j0 + 3] = h3;
        }
    };

    if (p == 0) {
        *(uint4*)(smem + SM_A0 + (unsigned)tok * PITCH + 224) = make_uint4(0, 0, 0, 0);
        *(uint4*)(smem + SM_A1 + (unsigned)tok * PITCH + 224) = make_uint4(0, 0, 0, 0);
    }

    float xaN, xbN;
    {
        float xa0 = __ldg(xpa), xb0 = __ldg(xpb);
        buildA(SM_A0, xa0, xb0);
        xaN = __ldg(xpa + 8u * 65536u);
        xbN = __ldg(xpb + 8u * 65536u);
    }

    for (int c = 0; c < NCHUNK; ++c) {
        const unsigned ab = sb + ((c & 1) ? SM_A1 : SM_A0);

        asm volatile("cp.async.wait_group 0;" ::: "memory");
        __syncthreads();

        if (c + 1 < NCHUNK) cpW(c + 1, (c + 1) & 1);

        // ---- MMA(c): f16 accumulators, 7 k-steps x 4 n16-groups ----
        unsigned hacc[8][2];
        #pragma unroll
        for (int t = 0; t < 8; ++t) hacc[t][0] = hacc[t][1] = 0u;

        const unsigned wb = sb + SM_W + (c & 1) * WBUF + hOff;
        unsigned a[7][4];
        #pragma unroll
        for (int ks = 0; ks < 7; ++ks) LDSM_X4(a[ks], ab + paBase + ks * 32);
        #pragma unroll
        for (int ng = 0; ng < 4; ++ng) {
            const unsigned base = wb + ng * 16 * PITCH + pbBase;
            #pragma unroll
            for (int ks = 0; ks < 7; ++ks) {
                unsigned b[4];
                LDSM_X4(b, base + ks * 32);
                MMA16816H(hacc[ng * 2],     a[ks], b[0], b[1]);
                MMA16816H(hacc[ng * 2 + 1], a[ks], b[2], b[3]);
            }
        }

        // ---- x(c+2) loads + build A(c+1) (overlaps MMA drain) ----
        float xa2 = 0.f, xb2 = 0.f;
        if (c + 2 < NCHUNK) {
            xa2 = __ldg(xpa + (size_t)(8 * (c + 2)) * 65536u);
            xb2 = __ldg(xpb + (size_t)(8 * (c + 2)) * 65536u);
        }
        if (c + 1 < NCHUNK)
            buildA(((c + 1) & 1) ? SM_A1 : SM_A0, xaN, xbN);
        xaN = xa2; xbN = xb2;

        // ---- promote chunk partials to f32 ----
        #pragma unroll
        for (int t = 0; t < 8; ++t) {
            __half2 d0 = *(__half2*)&hacc[t][0];
            __half2 d1 = *(__half2*)&hacc[t][1];
            acc[t][0] += __low2float(d0);  acc[t][1] += __high2float(d0);
            acc[t][2] += __low2float(d1);  acc[t][3] += __high2float(d1);
        }
    }

    // ---------------- epilogue: LN (cross n-half) + gamma/beta + residual ----
    float s0 = 0.f, q0 = 0.f, s1 = 0.f, q1 = 0.f;
    #pragma unroll
    for (int t = 0; t < 8; ++t) {
        s0 += acc[t][0] + acc[t][1];
        q0 = fmaf(acc[t][0], acc[t][0], fmaf(acc[t][1], acc[t][1], q0));
        s1 += acc[t][2] + acc[t][3];
        q1 = fmaf(acc[t][2], acc[t][2], fmaf(acc[t][3], acc[t][3], q1));
    }
    #pragma unroll
    for (int m = 1; m <= 2; m <<= 1) {
        s0 += __shfl_xor_sync(0xffffffffu, s0, m);
        q0 += __shfl_xor_sync(0xffffffffu, q0, m);
        s1 += __shfl_xor_sync(0xffffffffu, s1, m);
        q1 += __shfl_xor_sync(0xffffffffu, q1, m);
    }
    float2* epi = (float2*)(smem + SM_EPI);
    const int tr = g * 16 + (l >> 2);
    if ((l & 3) == 0) {
        epi[tr * 2 + h]       = make_float2(s0, q0);
        epi[(tr + 8) * 2 + h] = make_float2(s1, q1);
    }
    __syncthreads();
    float2 o0 = epi[tr * 2 + (h ^ 1)];
    float2 o1 = epi[(tr + 8) * 2 + (h ^ 1)];
    float mu0 = (s0 + o0.x) * (1.f / 128.f);
    float rs0 = rsqrtf(fmaf(q0 + o0.y, 1.f / 128.f, -mu0 * mu0) + LN_EPS);
    float mu1 = (s1 + o1.x) * (1.f / 128.f);
    float rs1 = rsqrtf(fmaf(q1 + o1.y, 1.f / 128.f, -mu1 * mu1) + LN_EPS);

    const int r0 = tokbase + tr;
    const int r1 = r0 + 8;
    const float* x0 = x + (size_t)r0 * 128;
    const float* x1 = x + (size_t)r1 * 128;
    float* out0 = out + (size_t)r0 * 128;
    float* out1 = out + (size_t)r1 * 128;
    #pragma unroll
    for (int t = 0; t < 8; ++t) {
        int n = h * 64 + (t >> 1) * 16 + (t & 1) * 8 + (l & 3) * 2;
        float4 gb = *(const float4*)(smem + SM_GB + n * 8);
        float2 xa = *(const float2*)(x0 + n);
        float2 xb = *(const float2*)(x1 + n);
        float2 oa, ob;
        oa.x = fmaf((acc[t][0] - mu0) * rs0, gb.x, gb.y) + xa.x;
        oa.y = fmaf((acc[t][1] - mu0) * rs0, gb.z, gb.w) + xa.y;
        ob.x = fmaf((acc[t][2] - mu1) * rs1, gb.x, gb.y) + xb.x;
        ob.y = fmaf((acc[t][3] - mu1) * rs1, gb.z, gb.w) + xb.y;
        *(float2*)(out0 + n) = oa;
        *(float2*)(out1 + n) = ob;
    }
}

// -------------------------------------------------------------------- launch
extern "C" void kernel_launch(void* const* d_in, const int* in_sizes, int n_in,
                              void* d_out, int out_size) {
    const float* x        = (const float*)d_in[0];
    const float* base_w   = (const float*)d_in[2];
    const float* spline_w = (const float*)d_in[3];
    const float* gamma    = (const float*)d_in[4];
    const float* beta     = (const float*)d_in[5];
    float* out            = (float*)d_out;

    transpose_x<<<2048, 256>>>(x);
    prep_w<<<960, 256>>>(base_w, spline_w);
    cudaFuncSetAttribute(kan_mma, cudaFuncAttributeMaxDynamicSharedMemorySize, SM_TOT);
    kan_mma<<<NCTA, 256, SM_TOT>>>(x, gamma, beta, out);
}